// round 8
// baseline (speedup 1.0000x reference)
#include <cuda_runtime.h>
#include <cuda_bf16.h>

#define MAX_N 100000
#define N_GRAPHS 64
#define FEAT 64
#define MAX_E 1600000

// ---------------- scratch (device globals; no allocations) ----------------
__device__ float          g_S[MAX_N * FEAT];   // aggregated neighbor means (fp32)
__device__ float          g_h[MAX_N * FEAT];   // layer output fp32
__device__ __nv_bfloat16  g_bf[MAX_N * FEAT];  // bf16 rows for gather (x, then h1)
__device__ int   g_deg[MAX_N];
__device__ int   g_rowstart[MAX_N + 1];
__device__ int   g_cursor[MAX_N];
__device__ int   g_srcs[MAX_E];
__device__ int   g_bsum[128];
__device__ int   g_boff[128];
__device__ float g_pooled[N_GRAPHS * FEAT];
__device__ int   g_ei64;
__device__ int   g_b64;

// ---------------- dtype detection (warp-parallel) ----------------
__global__ void detect_kernel(const void* ei, const void* batch, int nE, int nN) {
    int lane = threadIdx.x;
    const long long* p = (const long long*)ei;
    long long v = p[lane];
    int ok = (v >= 0 && v < (long long)nN);
    unsigned m = __ballot_sync(0xffffffffu, ok);
    int idx = nN / 2 - 1 - lane;
    long long bv = (idx >= 0) ? ((const long long*)batch)[idx] : 0;
    int bok = (bv >= 0 && bv < 64);
    unsigned bm = __ballot_sync(0xffffffffu, bok);
    if (lane == 0) {
        g_ei64 = (m == 0xffffffffu) ? 1 : 0;
        g_b64  = (bm == 0xffffffffu) ? 1 : 0;
    }
}

// ---------------- fp32 -> bf16 row conversion ----------------
__global__ void conv_bf16(const float* __restrict__ in, int n4) {
    int i = blockIdx.x * blockDim.x + threadIdx.x;
    if (i >= n4) return;
    float4 v = reinterpret_cast<const float4*>(in)[i];
    __nv_bfloat162 p0 = __float22bfloat162_rn(make_float2(v.x, v.y));
    __nv_bfloat162 p1 = __float22bfloat162_rn(make_float2(v.z, v.w));
    unsigned u0, u1;
    u0 = *reinterpret_cast<unsigned*>(&p0);
    u1 = *reinterpret_cast<unsigned*>(&p1);
    reinterpret_cast<uint2*>(g_bf)[i] = make_uint2(u0, u1);
}

// ---------------- CSR build ----------------
__global__ void zero_deg_kernel(int nN) {
    int i = blockIdx.x * blockDim.x + threadIdx.x;
    if (i < nN) g_deg[i] = 0;
}

__global__ void hist_kernel(const void* __restrict__ ei_v, int nE) {
    int e = blockIdx.x * blockDim.x + threadIdx.x;
    if (e >= nE) return;
    int dst;
    if (g_ei64) dst = (int)((const long long*)ei_v)[(long long)nE + e];
    else        dst = ((const int*)ei_v)[nE + e];
    atomicAdd(&g_deg[dst], 1);
}

__global__ void scan_block_kernel(int nN) {
    __shared__ int wsum[8];
    __shared__ int woff[8];
    int blk = blockIdx.x, t = threadIdx.x;
    int base = blk * 1024 + t * 4;
    int v0 = (base + 0 < nN) ? g_deg[base + 0] : 0;
    int v1 = (base + 1 < nN) ? g_deg[base + 1] : 0;
    int v2 = (base + 2 < nN) ? g_deg[base + 2] : 0;
    int v3 = (base + 3 < nN) ? g_deg[base + 3] : 0;
    int i0 = v0, i1 = i0 + v1, i2 = i1 + v2, i3 = i2 + v3;
    int tot = i3;
    int lane = t & 31, w = t >> 5;
    int sc = tot;
    #pragma unroll
    for (int off = 1; off < 32; off <<= 1) {
        int n = __shfl_up_sync(0xffffffffu, sc, off);
        if (lane >= off) sc += n;
    }
    if (lane == 31) wsum[w] = sc;
    __syncthreads();
    if (t < 8) {
        int v = wsum[t];
        int s = v;
        #pragma unroll
        for (int off = 1; off < 8; off <<= 1) {
            int n = __shfl_up_sync(0xffu, s, off);
            if (t >= off) s += n;
        }
        woff[t] = s - v;
        if (t == 7) g_bsum[blk] = s;
    }
    __syncthreads();
    int excl = woff[w] + (sc - tot);
    if (base + 0 < nN) g_rowstart[base + 0] = excl;
    if (base + 1 < nN) g_rowstart[base + 1] = excl + i0;
    if (base + 2 < nN) g_rowstart[base + 2] = excl + i1;
    if (base + 3 < nN) g_rowstart[base + 3] = excl + i2;
}

__global__ void scan_tops_kernel(int nBlocks) {
    __shared__ int wsum[4];
    __shared__ int woff[4];
    int t = threadIdx.x;
    int v = (t < nBlocks) ? g_bsum[t] : 0;
    int lane = t & 31, w = t >> 5;
    int s = v;
    #pragma unroll
    for (int off = 1; off < 32; off <<= 1) {
        int n = __shfl_up_sync(0xffffffffu, s, off);
        if (lane >= off) s += n;
    }
    if (lane == 31) wsum[w] = s;
    __syncthreads();
    if (t < 4) {
        int vv = wsum[t];
        int ss = vv;
        #pragma unroll
        for (int off = 1; off < 4; off <<= 1) {
            int n = __shfl_up_sync(0xfu, ss, off);
            if (t >= off) ss += n;
        }
        woff[t] = ss - vv;
    }
    __syncthreads();
    if (t < nBlocks) g_boff[t] = (s - v) + woff[w];
}

__global__ void scan_add_kernel(int nN, int nE) {
    int i = blockIdx.x * blockDim.x + threadIdx.x;
    if (i < nN) {
        int s = g_rowstart[i] + g_boff[i >> 10];
        g_rowstart[i] = s;
        g_cursor[i] = s;
    }
    if (i == 0) g_rowstart[nN] = nE;
}

__global__ void fill_kernel(const void* __restrict__ ei_v, int nE) {
    int e = blockIdx.x * blockDim.x + threadIdx.x;
    if (e >= nE) return;
    int src, dst;
    if (g_ei64) {
        const long long* ei = (const long long*)ei_v;
        src = (int)ei[e];
        dst = (int)ei[(long long)nE + e];
    } else {
        const int* ei = (const int*)ei_v;
        src = ei[e];
        dst = ei[nE + e];
    }
    int pos = atomicAdd(&g_cursor[dst], 1);
    g_srcs[pos] = src;
}

// ---------------- gather-mean: bf16 rows, shfl-broadcast indices ----------
// Rows are 64 bf16 = 128B: one LDG.32 warp-instruction per neighbor row
// (lane -> bf16x2). Half the L2 sector traffic of the fp32 version.
__global__ void gather_kernel(int nN) {
    int gtid = blockIdx.x * blockDim.x + threadIdx.x;
    int node = gtid >> 5;
    int lane = gtid & 31;
    if (node >= nN) return;
    const unsigned* base = reinterpret_cast<const unsigned*>(g_bf);
    int s = g_rowstart[node];
    int e = g_rowstart[node + 1];
    float ax = 0.f, ay = 0.f;

    for (int b = s; b < e; b += 32) {
        int cnt = min(32, e - b);
        int idxv = (lane < cnt) ? __ldg(&g_srcs[b + lane]) : 0;
        int j = 0;
        for (; j + 4 <= cnt; j += 4) {
            int a0 = __shfl_sync(0xffffffffu, idxv, j);
            int a1 = __shfl_sync(0xffffffffu, idxv, j + 1);
            int a2 = __shfl_sync(0xffffffffu, idxv, j + 2);
            int a3 = __shfl_sync(0xffffffffu, idxv, j + 3);
            unsigned u0 = __ldg(base + (size_t)a0 * 32 + lane);
            unsigned u1 = __ldg(base + (size_t)a1 * 32 + lane);
            unsigned u2 = __ldg(base + (size_t)a2 * 32 + lane);
            unsigned u3 = __ldg(base + (size_t)a3 * 32 + lane);
            float2 f0 = __bfloat1622float2(*reinterpret_cast<__nv_bfloat162*>(&u0));
            float2 f1 = __bfloat1622float2(*reinterpret_cast<__nv_bfloat162*>(&u1));
            float2 f2 = __bfloat1622float2(*reinterpret_cast<__nv_bfloat162*>(&u2));
            float2 f3 = __bfloat1622float2(*reinterpret_cast<__nv_bfloat162*>(&u3));
            ax += (f0.x + f1.x) + (f2.x + f3.x);
            ay += (f0.y + f1.y) + (f2.y + f3.y);
        }
        for (; j < cnt; j++) {
            int a0 = __shfl_sync(0xffffffffu, idxv, j);
            unsigned u0 = __ldg(base + (size_t)a0 * 32 + lane);
            float2 f0 = __bfloat1622float2(*reinterpret_cast<__nv_bfloat162*>(&u0));
            ax += f0.x; ay += f0.y;
        }
    }
    float inv = 1.0f / fmaxf((float)(e - s), 1.0f);
    reinterpret_cast<float2*>(g_S)[node * 32 + lane] = make_float2(ax * inv, ay * inv);
}

// ---------------- fused RGCN layer GEMM (proven scalar core) ----------
// writeBf: also emit bf16 copy of output rows (consumed by next gather).
__global__ void rgcn_gemm(const float* __restrict__ Xin,
                          const float* __restrict__ Wrel,
                          const float* __restrict__ Wroot,
                          const float* __restrict__ bias,
                          int nRows, int xIsH, int writeBf) {
    const float* X = xIsH ? (const float*)g_h : Xin;
    __shared__ float4 sW[128][16];
    __shared__ float4 sIn[64][33];
    __shared__ float  sB[64];

    int tid = threadIdx.x;
    int rowBase = blockIdx.x * 64;

    #pragma unroll
    for (int i = tid; i < 2048; i += 256) {
        int k = i >> 4, j = i & 15;
        sW[k][j] = (k < 64) ? reinterpret_cast<const float4*>(Wrel)[k * 16 + j]
                            : reinterpret_cast<const float4*>(Wroot)[(k - 64) * 16 + j];
    }
    if (tid < 64) sB[tid] = bias[tid];

    #pragma unroll
    for (int i = tid; i < 2048; i += 256) {
        int r = i >> 5, q = i & 31;
        int row = rowBase + r;
        float4 v = make_float4(0.f, 0.f, 0.f, 0.f);
        if (row < nRows) {
            if (q < 16) v = reinterpret_cast<const float4*>(g_S)[row * 16 + q];
            else        v = reinterpret_cast<const float4*>(X)[row * 16 + (q - 16)];
        }
        sIn[r][q] = v;
    }
    __syncthreads();

    int tx = tid & 15;
    int ty = tid >> 4;
    float acc[4][4];
    #pragma unroll
    for (int i = 0; i < 4; i++)
        #pragma unroll
        for (int j = 0; j < 4; j++) acc[i][j] = 0.f;

    #pragma unroll 8
    for (int k4 = 0; k4 < 32; ++k4) {
        float4 a0 = sIn[ty      ][k4];
        float4 a1 = sIn[ty + 16][k4];
        float4 a2 = sIn[ty + 32][k4];
        float4 a3 = sIn[ty + 48][k4];
        float4 w0 = sW[4 * k4 + 0][tx];
        float4 w1 = sW[4 * k4 + 1][tx];
        float4 w2 = sW[4 * k4 + 2][tx];
        float4 w3 = sW[4 * k4 + 3][tx];
        float4 a[4] = {a0, a1, a2, a3};
        #pragma unroll
        for (int i = 0; i < 4; i++) {
            acc[i][0] += a[i].x * w0.x + a[i].y * w1.x + a[i].z * w2.x + a[i].w * w3.x;
            acc[i][1] += a[i].x * w0.y + a[i].y * w1.y + a[i].z * w2.y + a[i].w * w3.y;
            acc[i][2] += a[i].x * w0.z + a[i].y * w1.z + a[i].z * w2.z + a[i].w * w3.z;
            acc[i][3] += a[i].x * w0.w + a[i].y * w1.w + a[i].z * w2.w + a[i].w * w3.w;
        }
    }

    #pragma unroll
    for (int i = 0; i < 4; i++) {
        int row = rowBase + ty + 16 * i;
        if (row < nRows) {
            float4 o;
            o.x = fmaxf(acc[i][0] + sB[tx * 4 + 0], 0.f);
            o.y = fmaxf(acc[i][1] + sB[tx * 4 + 1], 0.f);
            o.z = fmaxf(acc[i][2] + sB[tx * 4 + 2], 0.f);
            o.w = fmaxf(acc[i][3] + sB[tx * 4 + 3], 0.f);
            reinterpret_cast<float4*>(g_h)[row * 16 + tx] = o;
            if (writeBf) {
                __nv_bfloat162 p0 = __float22bfloat162_rn(make_float2(o.x, o.y));
                __nv_bfloat162 p1 = __float22bfloat162_rn(make_float2(o.z, o.w));
                unsigned u0 = *reinterpret_cast<unsigned*>(&p0);
                unsigned u1 = *reinterpret_cast<unsigned*>(&p1);
                reinterpret_cast<uint2*>(g_bf)[row * 16 + tx] = make_uint2(u0, u1);
            }
        }
    }
}

// ---------------- global mean pool (reads g_h) ----------------
__device__ __forceinline__ long long batch_at(const void* b, int i, int is64) {
    return is64 ? ((const long long*)b)[i] : (long long)((const int*)b)[i];
}

__global__ void pool_kernel(const void* __restrict__ batch, int nRows) {
    int g = blockIdx.x;
    int is64 = g_b64;
    int lo = 0, hi = nRows;
    while (lo < hi) { int m = (lo + hi) >> 1; if (batch_at(batch, m, is64) < g) lo = m + 1; else hi = m; }
    int start = lo;
    lo = 0; hi = nRows;
    while (lo < hi) { int m = (lo + hi) >> 1; if (batch_at(batch, m, is64) < g + 1) lo = m + 1; else hi = m; }
    int end = lo;

    int feat = threadIdx.x & 63;
    int rl   = threadIdx.x >> 6;
    float s = 0.f;
    for (int r = start + rl; r < end; r += 4)
        s += g_h[(long long)r * FEAT + feat];

    __shared__ float sm[4][64];
    sm[rl][feat] = s;
    __syncthreads();
    if (rl == 0) {
        float tot = sm[0][feat] + sm[1][feat] + sm[2][feat] + sm[3][feat];
        g_pooled[g * FEAT + feat] = tot / fmaxf((float)(end - start), 1.0f);
    }
}

// ---------------- heads ----------------
__global__ void head_kernel(const float* __restrict__ Wh, const float* __restrict__ bh,
                            const float* __restrict__ Wc, const float* __restrict__ bc,
                            const float* __restrict__ Wo, const float* __restrict__ bo,
                            float* __restrict__ out) {
    __shared__ float sp[64 * 64];
    __shared__ float sh[64 * 64];
    int tid = threadIdx.x;

    for (int i = tid; i < 4096; i += 256) sp[i] = g_pooled[i];
    __syncthreads();

    for (int i = tid; i < 4096; i += 256) {
        int g = i >> 6, j = i & 63;
        float ah = bh[j], ac = bc[j];
        #pragma unroll 8
        for (int k = 0; k < 64; k++) {
            float p = sp[g * 64 + k];
            ah += p * Wh[k * 64 + j];
            ac += p * Wc[k * 64 + j];
        }
        sh[i] = ah;
        out[2048 + i] = ah;
        out[2048 + 4096 + i] = ac;
    }
    __syncthreads();

    int warp = tid >> 5, lane = tid & 31;
    for (int g = warp; g < 64; g += 8) {
        float z = bo[lane];
        #pragma unroll 8
        for (int k = 0; k < 64; k++)
            z += sh[g * 64 + k] * Wo[k * 32 + lane];
        float m = z;
        #pragma unroll
        for (int off = 16; off > 0; off >>= 1)
            m = fmaxf(m, __shfl_xor_sync(0xffffffffu, m, off));
        float s = expf(z - m);
        #pragma unroll
        for (int off = 16; off > 0; off >>= 1)
            s += __shfl_xor_sync(0xffffffffu, s, off);
        out[g * 32 + lane] = z - m - logf(s);
    }
}

// ---------------- launch ----------------
extern "C" void kernel_launch(void* const* d_in, const int* in_sizes, int n_in,
                              void* d_out, int out_size) {
    const float* x     = (const float*)d_in[0];
    const void*  ei    = d_in[1];
    const void*  batch = d_in[2];
    const float* W1    = (const float*)d_in[3];
    const float* root1 = (const float*)d_in[4];
    const float* b1    = (const float*)d_in[5];
    const float* W2    = (const float*)d_in[6];
    const float* root2 = (const float*)d_in[7];
    const float* b2    = (const float*)d_in[8];
    const float* Wh    = (const float*)d_in[9];
    const float* bh    = (const float*)d_in[10];
    const float* Wc    = (const float*)d_in[11];
    const float* bc    = (const float*)d_in[12];
    const float* Wo    = (const float*)d_in[13];
    const float* bo    = (const float*)d_in[14];

    int nN = in_sizes[0] / FEAT;   // 100000
    int nE = in_sizes[1] / 2;      // 1600000

    int eBlocks = (nE + 255) / 256;
    int nBlocks = (nN + 255) / 256;
    int scanBlocks = (nN + 1023) / 1024;
    int gatherBlocks = (nN * 32 + 255) / 256;
    int gemmBlocks = (nN + 63) / 64;
    int convBlocks = (nN * 16 + 255) / 256;

    detect_kernel<<<1, 32>>>(ei, batch, nE, nN);

    // CSR build
    zero_deg_kernel<<<nBlocks, 256>>>(nN);
    hist_kernel<<<eBlocks, 256>>>(ei, nE);
    scan_block_kernel<<<scanBlocks, 256>>>(nN);
    scan_tops_kernel<<<1, 128>>>(scanBlocks);
    scan_add_kernel<<<nBlocks, 256>>>(nN, nE);
    fill_kernel<<<eBlocks, 256>>>(ei, nE);

    // layer 1: x -> bf16, gather bf16, GEMM (write fp32 + bf16 h1)
    conv_bf16<<<convBlocks, 256>>>(x, nN * 16);
    gather_kernel<<<gatherBlocks, 256>>>(nN);
    rgcn_gemm<<<gemmBlocks, 256>>>(x, W1, root1, b1, nN, 0, 1);

    // layer 2: gather bf16 h1, GEMM (fp32 only, in-place g_h)
    gather_kernel<<<gatherBlocks, 256>>>(nN);
    rgcn_gemm<<<gemmBlocks, 256>>>(x, W2, root2, b2, nN, 1, 0);

    // pool + heads
    pool_kernel<<<N_GRAPHS, 256>>>(batch, nN);
    head_kernel<<<1, 256>>>(Wh, bh, Wc, bc, Wo, bo, (float*)d_out);
}

// round 10
// speedup vs baseline: 1.0886x; 1.0886x over previous
#include <cuda_runtime.h>
#include <cuda_bf16.h>
#include <mma.h>
#include <cstdint>

using namespace nvcuda;

#define MAX_N 100000
#define N_GRAPHS 64
#define FEAT 64
#define MAX_E 1600000

// ---------------- scratch ----------------
__device__ float g_S[MAX_N * FEAT];
__device__ float g_h[MAX_N * FEAT];
__device__ float g_h2[MAX_N * FEAT];
__device__ int   g_deg[MAX_N];
__device__ int   g_rowstart[MAX_N + 1];
__device__ int   g_cursor[MAX_N];
__device__ int   g_srcs[MAX_E];
__device__ int   g_bsum[128];
__device__ int   g_boff[128];
__device__ float g_pooled[N_GRAPHS * FEAT];
__device__ int   g_ei64;
__device__ int   g_b64;

// ---------------- dtype detection ----------------
__global__ void detect_kernel(const void* ei, const void* batch, int nE, int nN) {
    int lane = threadIdx.x;
    const long long* p = (const long long*)ei;
    long long v = p[lane];
    int ok = (v >= 0 && v < (long long)nN);
    unsigned m = __ballot_sync(0xffffffffu, ok);
    int idx = nN / 2 - 1 - lane;
    long long bv = (idx >= 0) ? ((const long long*)batch)[idx] : 0;
    int bok = (bv >= 0 && bv < 64);
    unsigned bm = __ballot_sync(0xffffffffu, bok);
    if (lane == 0) {
        g_ei64 = (m == 0xffffffffu) ? 1 : 0;
        g_b64  = (bm == 0xffffffffu) ? 1 : 0;
    }
}

// ---------------- CSR build ----------------
__global__ void zero_deg_kernel(int nN) {
    int i = blockIdx.x * blockDim.x + threadIdx.x;
    if (i < nN) g_deg[i] = 0;
}

__global__ void hist_kernel(const void* __restrict__ ei_v, int nE) {
    int e = blockIdx.x * blockDim.x + threadIdx.x;
    if (e >= nE) return;
    int dst;
    if (g_ei64) dst = (int)((const long long*)ei_v)[(long long)nE + e];
    else        dst = ((const int*)ei_v)[nE + e];
    atomicAdd(&g_deg[dst], 1);
}

__global__ void scan_block_kernel(int nN) {
    __shared__ int wsum[8];
    __shared__ int woff[8];
    int blk = blockIdx.x, t = threadIdx.x;
    int base = blk * 1024 + t * 4;
    int v0 = (base + 0 < nN) ? g_deg[base + 0] : 0;
    int v1 = (base + 1 < nN) ? g_deg[base + 1] : 0;
    int v2 = (base + 2 < nN) ? g_deg[base + 2] : 0;
    int v3 = (base + 3 < nN) ? g_deg[base + 3] : 0;
    int i0 = v0, i1 = i0 + v1, i2 = i1 + v2, i3 = i2 + v3;
    int tot = i3;
    int lane = t & 31, w = t >> 5;
    int sc = tot;
    #pragma unroll
    for (int off = 1; off < 32; off <<= 1) {
        int n = __shfl_up_sync(0xffffffffu, sc, off);
        if (lane >= off) sc += n;
    }
    if (lane == 31) wsum[w] = sc;
    __syncthreads();
    if (t < 8) {
        int v = wsum[t];
        int s = v;
        #pragma unroll
        for (int off = 1; off < 8; off <<= 1) {
            int n = __shfl_up_sync(0xffu, s, off);
            if (t >= off) s += n;
        }
        woff[t] = s - v;
        if (t == 7) g_bsum[blk] = s;
    }
    __syncthreads();
    int excl = woff[w] + (sc - tot);
    if (base + 0 < nN) g_rowstart[base + 0] = excl;
    if (base + 1 < nN) g_rowstart[base + 1] = excl + i0;
    if (base + 2 < nN) g_rowstart[base + 2] = excl + i1;
    if (base + 3 < nN) g_rowstart[base + 3] = excl + i2;
}

__global__ void scan_tops_kernel(int nBlocks) {
    __shared__ int wsum[4];
    __shared__ int woff[4];
    int t = threadIdx.x;
    int v = (t < nBlocks) ? g_bsum[t] : 0;
    int lane = t & 31, w = t >> 5;
    int s = v;
    #pragma unroll
    for (int off = 1; off < 32; off <<= 1) {
        int n = __shfl_up_sync(0xffffffffu, s, off);
        if (lane >= off) s += n;
    }
    if (lane == 31) wsum[w] = s;
    __syncthreads();
    if (t < 4) {
        int vv = wsum[t];
        int ss = vv;
        #pragma unroll
        for (int off = 1; off < 4; off <<= 1) {
            int n = __shfl_up_sync(0xfu, ss, off);
            if (t >= off) ss += n;
        }
        woff[t] = ss - vv;
    }
    __syncthreads();
    if (t < nBlocks) g_boff[t] = (s - v) + woff[w];
}

__global__ void scan_add_kernel(int nN, int nE) {
    int i = blockIdx.x * blockDim.x + threadIdx.x;
    if (i < nN) {
        int s = g_rowstart[i] + g_boff[i >> 10];
        g_rowstart[i] = s;
        g_cursor[i] = s;
    }
    if (i == 0) g_rowstart[nN] = nE;
}

__global__ void fill_kernel(const void* __restrict__ ei_v, int nE) {
    int e = blockIdx.x * blockDim.x + threadIdx.x;
    if (e >= nE) return;
    int src, dst;
    if (g_ei64) {
        const long long* ei = (const long long*)ei_v;
        src = (int)ei[e];
        dst = (int)ei[(long long)nE + e];
    } else {
        const int* ei = (const int*)ei_v;
        src = ei[e];
        dst = ei[nE + e];
    }
    int pos = atomicAdd(&g_cursor[dst], 1);
    g_srcs[pos] = src;
}

// ---------------- gather-mean (R7 fp32 form) ----------------
__global__ void gather_kernel(const float* __restrict__ x, int nN, int fromH) {
    int gtid = blockIdx.x * blockDim.x + threadIdx.x;
    int node = gtid >> 5;
    int lane = gtid & 31;
    if (node >= nN) return;
    const float* base = fromH ? (const float*)g_h : x;
    int s = g_rowstart[node];
    int e = g_rowstart[node + 1];
    float ax = 0.f, ay = 0.f;

    for (int b = s; b < e; b += 32) {
        int cnt = min(32, e - b);
        int idxv = (lane < cnt) ? __ldg(&g_srcs[b + lane]) : 0;
        int j = 0;
        for (; j + 4 <= cnt; j += 4) {
            int a0 = __shfl_sync(0xffffffffu, idxv, j);
            int a1 = __shfl_sync(0xffffffffu, idxv, j + 1);
            int a2 = __shfl_sync(0xffffffffu, idxv, j + 2);
            int a3 = __shfl_sync(0xffffffffu, idxv, j + 3);
            float2 v0 = __ldg((const float2*)(base + (size_t)a0 * FEAT) + lane);
            float2 v1 = __ldg((const float2*)(base + (size_t)a1 * FEAT) + lane);
            float2 v2 = __ldg((const float2*)(base + (size_t)a2 * FEAT) + lane);
            float2 v3 = __ldg((const float2*)(base + (size_t)a3 * FEAT) + lane);
            ax += (v0.x + v1.x) + (v2.x + v3.x);
            ay += (v0.y + v1.y) + (v2.y + v3.y);
        }
        for (; j < cnt; j++) {
            int a0 = __shfl_sync(0xffffffffu, idxv, j);
            float2 v0 = __ldg((const float2*)(base + (size_t)a0 * FEAT) + lane);
            ax += v0.x; ay += v0.y;
        }
    }
    float inv = 1.0f / fmaxf((float)(e - s), 1.0f);
    reinterpret_cast<float2*>(g_S)[node * 32 + lane] = make_float2(ax * inv, ay * inv);
}

// ---------------- wmma bf16 fused layer GEMM ------------------------------
// out = relu([S|X](bf16) @ [Wrel;Wroot](bf16) + b)
// Block: 128 rows x 64 cols, 8 warps; warp w -> rows 16w..16w+15.
// A smem: 128 x 136 bf16 (padded); B smem: 128 x 72 bf16 (padded).
#define A_LD 136
#define B_LD 72
__global__ void __launch_bounds__(256, 2)
mma_layer(const float* __restrict__ Xin,
          const float* __restrict__ Wrel,
          const float* __restrict__ Wroot,
          const float* __restrict__ bias,
          float* __restrict__ out,
          int nRows) {
    extern __shared__ char dyn[];
    __nv_bfloat16* sA = reinterpret_cast<__nv_bfloat16*>(dyn);            // 128*136*2 = 34816B
    __nv_bfloat16* sB = reinterpret_cast<__nv_bfloat16*>(dyn + 34816);    // 128*72*2  = 18432B
    float* stage = reinterpret_cast<float*>(dyn);                         // reused post-compute
    __shared__ float s_bias[64];

    int tid = threadIdx.x;
    int warp = tid >> 5;
    int rowBase = blockIdx.x * 128;

    if (tid < 64) s_bias[tid] = bias[tid];

    // ---- B tile: [k][n] bf16, k<64: Wrel, k>=64: Wroot ----
    for (int i = tid; i < 128 * 32; i += 256) {     // 2 cols per item
        int k = i >> 5, n2 = i & 31;
        int n = n2 * 2;
        float2 w = (k < 64)
            ? *reinterpret_cast<const float2*>(Wrel + k * 64 + n)
            : *reinterpret_cast<const float2*>(Wroot + (k - 64) * 64 + n);
        *reinterpret_cast<__nv_bfloat162*>(sB + k * B_LD + n) = __float22bfloat162_rn(w);
    }

    // ---- A tile: [r][k] bf16, k<64: S row, k>=64: X row ----
    for (int i = tid; i < 128 * 64; i += 256) {     // 2 ks per item
        int r = i >> 6, k2 = i & 63;
        int k = k2 * 2;
        int grow = rowBase + r;
        float2 v = make_float2(0.f, 0.f);
        if (grow < nRows) {
            if (k < 64) v = *reinterpret_cast<const float2*>(g_S + (size_t)grow * 64 + k);
            else        v = *reinterpret_cast<const float2*>(Xin + (size_t)grow * 64 + (k - 64));
        }
        *reinterpret_cast<__nv_bfloat162*>(sA + r * A_LD + k) = __float22bfloat162_rn(v);
    }
    __syncthreads();

    // ---- compute: each warp 16x64 strip ----
    wmma::fragment<wmma::accumulator, 16, 16, 16, float> acc[4];
    #pragma unroll
    for (int j = 0; j < 4; j++) wmma::fill_fragment(acc[j], 0.0f);

    #pragma unroll
    for (int ks = 0; ks < 8; ks++) {
        wmma::fragment<wmma::matrix_a, 16, 16, 16, __nv_bfloat16, wmma::row_major> aF;
        wmma::load_matrix_sync(aF, sA + (warp * 16) * A_LD + ks * 16, A_LD);
        #pragma unroll
        for (int j = 0; j < 4; j++) {
            wmma::fragment<wmma::matrix_b, 16, 16, 16, __nv_bfloat16, wmma::row_major> bF;
            wmma::load_matrix_sync(bF, sB + (ks * 16) * B_LD + j * 16, B_LD);
            wmma::mma_sync(acc[j], aF, bF, acc[j]);
        }
    }
    __syncthreads();   // done reading sA/sB; stage aliases dyn

    // ---- epilogue: store frags to stage (128 x 68 f32), bias+relu on way out
    #pragma unroll
    for (int j = 0; j < 4; j++)
        wmma::store_matrix_sync(stage + (warp * 16) * 68 + j * 16, acc[j], 68,
                                wmma::mem_row_major);
    __syncthreads();

    for (int i = tid; i < 128 * 64; i += 256) {
        int r = i >> 6, c = i & 63;
        int grow = rowBase + r;
        if (grow < nRows) {
            float v = stage[r * 68 + c] + s_bias[c];
            out[(size_t)grow * 64 + c] = fmaxf(v, 0.f);
        }
    }
}

// ---------------- global mean pool (reads g_h2) ----------------
__device__ __forceinline__ long long batch_at(const void* b, int i, int is64) {
    return is64 ? ((const long long*)b)[i] : (long long)((const int*)b)[i];
}

__global__ void pool_kernel(const void* __restrict__ batch, int nRows) {
    int g = blockIdx.x;
    int is64 = g_b64;
    int lo = 0, hi = nRows;
    while (lo < hi) { int m = (lo + hi) >> 1; if (batch_at(batch, m, is64) < g) lo = m + 1; else hi = m; }
    int start = lo;
    lo = 0; hi = nRows;
    while (lo < hi) { int m = (lo + hi) >> 1; if (batch_at(batch, m, is64) < g + 1) lo = m + 1; else hi = m; }
    int end = lo;

    int feat = threadIdx.x & 63;
    int rl   = threadIdx.x >> 6;
    float s = 0.f;
    for (int r = start + rl; r < end; r += 4)
        s += g_h2[(long long)r * FEAT + feat];

    __shared__ float sm[4][64];
    sm[rl][feat] = s;
    __syncthreads();
    if (rl == 0) {
        float tot = sm[0][feat] + sm[1][feat] + sm[2][feat] + sm[3][feat];
        g_pooled[g * FEAT + feat] = tot / fmaxf((float)(end - start), 1.0f);
    }
}

// ---------------- heads ----------------
__global__ void head_kernel(const float* __restrict__ Wh, const float* __restrict__ bh,
                            const float* __restrict__ Wc, const float* __restrict__ bc,
                            const float* __restrict__ Wo, const float* __restrict__ bo,
                            float* __restrict__ out) {
    __shared__ float sp[64 * 64];
    __shared__ float sh[64 * 64];
    int tid = threadIdx.x;

    for (int i = tid; i < 4096; i += 256) sp[i] = g_pooled[i];
    __syncthreads();

    for (int i = tid; i < 4096; i += 256) {
        int g = i >> 6, j = i & 63;
        float ah = bh[j], ac = bc[j];
        #pragma unroll 8
        for (int k = 0; k < 64; k++) {
            float p = sp[g * 64 + k];
            ah += p * Wh[k * 64 + j];
            ac += p * Wc[k * 64 + j];
        }
        sh[i] = ah;
        out[2048 + i] = ah;
        out[2048 + 4096 + i] = ac;
    }
    __syncthreads();

    int warp = tid >> 5, lane = tid & 31;
    for (int g = warp; g < 64; g += 8) {
        float z = bo[lane];
        #pragma unroll 8
        for (int k = 0; k < 64; k++)
            z += sh[g * 64 + k] * Wo[k * 32 + lane];
        float m = z;
        #pragma unroll
        for (int off = 16; off > 0; off >>= 1)
            m = fmaxf(m, __shfl_xor_sync(0xffffffffu, m, off));
        float s = expf(z - m);
        #pragma unroll
        for (int off = 16; off > 0; off >>= 1)
            s += __shfl_xor_sync(0xffffffffu, s, off);
        out[g * 32 + lane] = z - m - logf(s);
    }
}

// ---------------- launch ----------------
extern "C" void kernel_launch(void* const* d_in, const int* in_sizes, int n_in,
                              void* d_out, int out_size) {
    const float* x     = (const float*)d_in[0];
    const void*  ei    = d_in[1];
    const void*  batch = d_in[2];
    const float* W1    = (const float*)d_in[3];
    const float* root1 = (const float*)d_in[4];
    const float* b1    = (const float*)d_in[5];
    const float* W2    = (const float*)d_in[6];
    const float* root2 = (const float*)d_in[7];
    const float* b2    = (const float*)d_in[8];
    const float* Wh    = (const float*)d_in[9];
    const float* bh    = (const float*)d_in[10];
    const float* Wc    = (const float*)d_in[11];
    const float* bc    = (const float*)d_in[12];
    const float* Wo    = (const float*)d_in[13];
    const float* bo    = (const float*)d_in[14];

    int nN = in_sizes[0] / FEAT;   // 100000
    int nE = in_sizes[1] / 2;      // 1600000

    int eBlocks = (nE + 255) / 256;
    int nBlocks = (nN + 255) / 256;
    int scanBlocks = (nN + 1023) / 1024;
    int gatherBlocks = (nN * 32 + 255) / 256;
    int mmaBlocks = (nN + 127) / 128;
    size_t dynBytes = 34816 + 18432;   // A + B tiles (53.2KB > stage 34.8KB)

    float* h1 = nullptr; float* h2 = nullptr;
    cudaGetSymbolAddress((void**)&h1, g_h);
    cudaGetSymbolAddress((void**)&h2, g_h2);

    static int smemSet = 0;
    if (!smemSet) {
        cudaFuncSetAttribute(mma_layer, cudaFuncAttributeMaxDynamicSharedMemorySize,
                             (int)dynBytes);
        smemSet = 1;
    }

    detect_kernel<<<1, 32>>>(ei, batch, nE, nN);

    // CSR build
    zero_deg_kernel<<<nBlocks, 256>>>(nN);
    hist_kernel<<<eBlocks, 256>>>(ei, nE);
    scan_block_kernel<<<scanBlocks, 256>>>(nN);
    scan_tops_kernel<<<1, 128>>>(scanBlocks);
    scan_add_kernel<<<nBlocks, 256>>>(nN, nE);
    fill_kernel<<<eBlocks, 256>>>(ei, nE);

    // layer 1
    gather_kernel<<<gatherBlocks, 256>>>(x, nN, 0);
    mma_layer<<<mmaBlocks, 256, dynBytes>>>(x, W1, root1, b1, h1, nN);

    // layer 2
    gather_kernel<<<gatherBlocks, 256>>>(x, nN, 1);
    mma_layer<<<mmaBlocks, 256, dynBytes>>>(h1, W2, root2, b2, h2, nN);

    // pool + heads
    pool_kernel<<<N_GRAPHS, 256>>>(batch, nN);
    head_kernel<<<1, 256>>>(Wh, bh, Wc, bc, Wo, bo, (float*)d_out);
}

// round 11
// speedup vs baseline: 1.3871x; 1.2742x over previous
#include <cuda_runtime.h>
#include <cuda_bf16.h>
#include <mma.h>
#include <cstdint>

using namespace nvcuda;

#define MAX_N 100000
#define N_GRAPHS 64
#define FEAT 64
#define MAX_E 1600000

// ---------------- scratch ----------------
__device__ float g_S[MAX_N * FEAT];
__device__ float g_h[MAX_N * FEAT];
__device__ float g_h2[MAX_N * FEAT];
__device__ int   g_deg[MAX_N];
__device__ int   g_rowstart[MAX_N + 1];
__device__ int   g_cursor[MAX_N];
__device__ int   g_srcs[MAX_E];
__device__ int   g_bsum[128];
__device__ int   g_boff[128];
__device__ int   g_ei64;
__device__ int   g_b64;

// ---------------- zero degree + dtype detection (merged) ----------------
__global__ void zero_detect_kernel(const void* ei, const void* batch, int nE, int nN) {
    int i = blockIdx.x * blockDim.x + threadIdx.x;
    if (i < nN) g_deg[i] = 0;
    if (blockIdx.x == 0 && threadIdx.x < 32) {
        int lane = threadIdx.x;
        const long long* p = (const long long*)ei;
        long long v = p[lane];
        int ok = (v >= 0 && v < (long long)nN);
        unsigned m = __ballot_sync(0xffffffffu, ok);
        int idx = nN / 2 - 1 - lane;
        long long bv = (idx >= 0) ? ((const long long*)batch)[idx] : 0;
        int bok = (bv >= 0 && bv < 64);
        unsigned bm = __ballot_sync(0xffffffffu, bok);
        if (lane == 0) {
            g_ei64 = (m == 0xffffffffu) ? 1 : 0;
            g_b64  = (bm == 0xffffffffu) ? 1 : 0;
        }
    }
}

// ---------------- CSR build ----------------
__global__ void hist_kernel(const void* __restrict__ ei_v, int nE) {
    int e = blockIdx.x * blockDim.x + threadIdx.x;
    if (e >= nE) return;
    int dst;
    if (g_ei64) dst = (int)((const long long*)ei_v)[(long long)nE + e];
    else        dst = ((const int*)ei_v)[nE + e];
    atomicAdd(&g_deg[dst], 1);
}

__global__ void scan_block_kernel(int nN) {
    __shared__ int wsum[8];
    __shared__ int woff[8];
    int blk = blockIdx.x, t = threadIdx.x;
    int base = blk * 1024 + t * 4;
    int v0 = (base + 0 < nN) ? g_deg[base + 0] : 0;
    int v1 = (base + 1 < nN) ? g_deg[base + 1] : 0;
    int v2 = (base + 2 < nN) ? g_deg[base + 2] : 0;
    int v3 = (base + 3 < nN) ? g_deg[base + 3] : 0;
    int i0 = v0, i1 = i0 + v1, i2 = i1 + v2, i3 = i2 + v3;
    int tot = i3;
    int lane = t & 31, w = t >> 5;
    int sc = tot;
    #pragma unroll
    for (int off = 1; off < 32; off <<= 1) {
        int n = __shfl_up_sync(0xffffffffu, sc, off);
        if (lane >= off) sc += n;
    }
    if (lane == 31) wsum[w] = sc;
    __syncthreads();
    if (t < 8) {
        int v = wsum[t];
        int s = v;
        #pragma unroll
        for (int off = 1; off < 8; off <<= 1) {
            int n = __shfl_up_sync(0xffu, s, off);
            if (t >= off) s += n;
        }
        woff[t] = s - v;
        if (t == 7) g_bsum[blk] = s;
    }
    __syncthreads();
    int excl = woff[w] + (sc - tot);
    if (base + 0 < nN) g_rowstart[base + 0] = excl;
    if (base + 1 < nN) g_rowstart[base + 1] = excl + i0;
    if (base + 2 < nN) g_rowstart[base + 2] = excl + i1;
    if (base + 3 < nN) g_rowstart[base + 3] = excl + i2;
}

__global__ void scan_tops_kernel(int nBlocks) {
    __shared__ int wsum[4];
    __shared__ int woff[4];
    int t = threadIdx.x;
    int v = (t < nBlocks) ? g_bsum[t] : 0;
    int lane = t & 31, w = t >> 5;
    int s = v;
    #pragma unroll
    for (int off = 1; off < 32; off <<= 1) {
        int n = __shfl_up_sync(0xffffffffu, s, off);
        if (lane >= off) s += n;
    }
    if (lane == 31) wsum[w] = s;
    __syncthreads();
    if (t < 4) {
        int vv = wsum[t];
        int ss = vv;
        #pragma unroll
        for (int off = 1; off < 4; off <<= 1) {
            int n = __shfl_up_sync(0xfu, ss, off);
            if (t >= off) ss += n;
        }
        woff[t] = ss - vv;
    }
    __syncthreads();
    if (t < nBlocks) g_boff[t] = (s - v) + woff[w];
}

__global__ void scan_add_kernel(int nN, int nE) {
    int i = blockIdx.x * blockDim.x + threadIdx.x;
    if (i < nN) {
        int s = g_rowstart[i] + g_boff[i >> 10];
        g_rowstart[i] = s;
        g_cursor[i] = s;
    }
    if (i == 0) g_rowstart[nN] = nE;
}

__global__ void fill_kernel(const void* __restrict__ ei_v, int nE) {
    int e = blockIdx.x * blockDim.x + threadIdx.x;
    if (e >= nE) return;
    int src, dst;
    if (g_ei64) {
        const long long* ei = (const long long*)ei_v;
        src = (int)ei[e];
        dst = (int)ei[(long long)nE + e];
    } else {
        const int* ei = (const int*)ei_v;
        src = ei[e];
        dst = ei[nE + e];
    }
    int pos = atomicAdd(&g_cursor[dst], 1);
    g_srcs[pos] = src;
}

// ---------------- gather-mean (R7 fp32 form) ----------------
__global__ void gather_kernel(const float* __restrict__ x, int nN, int fromH) {
    int gtid = blockIdx.x * blockDim.x + threadIdx.x;
    int node = gtid >> 5;
    int lane = gtid & 31;
    if (node >= nN) return;
    const float* base = fromH ? (const float*)g_h : x;
    int s = g_rowstart[node];
    int e = g_rowstart[node + 1];
    float ax = 0.f, ay = 0.f;

    for (int b = s; b < e; b += 32) {
        int cnt = min(32, e - b);
        int idxv = (lane < cnt) ? __ldg(&g_srcs[b + lane]) : 0;
        int j = 0;
        for (; j + 4 <= cnt; j += 4) {
            int a0 = __shfl_sync(0xffffffffu, idxv, j);
            int a1 = __shfl_sync(0xffffffffu, idxv, j + 1);
            int a2 = __shfl_sync(0xffffffffu, idxv, j + 2);
            int a3 = __shfl_sync(0xffffffffu, idxv, j + 3);
            float2 v0 = __ldg((const float2*)(base + (size_t)a0 * FEAT) + lane);
            float2 v1 = __ldg((const float2*)(base + (size_t)a1 * FEAT) + lane);
            float2 v2 = __ldg((const float2*)(base + (size_t)a2 * FEAT) + lane);
            float2 v3 = __ldg((const float2*)(base + (size_t)a3 * FEAT) + lane);
            ax += (v0.x + v1.x) + (v2.x + v3.x);
            ay += (v0.y + v1.y) + (v2.y + v3.y);
        }
        for (; j < cnt; j++) {
            int a0 = __shfl_sync(0xffffffffu, idxv, j);
            float2 v0 = __ldg((const float2*)(base + (size_t)a0 * FEAT) + lane);
            ax += v0.x; ay += v0.y;
        }
    }
    float inv = 1.0f / fmaxf((float)(e - s), 1.0f);
    reinterpret_cast<float2*>(g_S)[node * 32 + lane] = make_float2(ax * inv, ay * inv);
}

// ---------------- wmma tf32 fused layer GEMM ------------------------------
// out = relu([S|X](tf32) @ [Wrel;Wroot](tf32) + b), fp32 accumulate.
// Block: 128 rows x 64 cols, 8 warps; warp w -> rows 16w..16w+15.
// A smem: 128 x 72 f32 (tf32-rounded); B smem: 128 x 68 f32.
#define A_LDF 72
#define B_LDF 68
__global__ void __launch_bounds__(256, 3)
mma_layer(const float* __restrict__ Xin,
          const float* __restrict__ Wrel,
          const float* __restrict__ Wroot,
          const float* __restrict__ bias,
          float* __restrict__ out,
          int nRows) {
    extern __shared__ float dynf[];
    float* sA = dynf;                 // 128*72*4 = 36864B
    float* sB = dynf + 128 * A_LDF;   // 128*68*4 = 34816B
    float* stage = dynf;              // reused post-compute (128*68*4)
    __shared__ float s_bias[64];

    int tid = threadIdx.x;
    int warp = tid >> 5;
    int rowBase = blockIdx.x * 128;

    if (tid < 64) s_bias[tid] = bias[tid];

    // ---- B tile: [k][n], tf32-rounded ----
    for (int i = tid; i < 128 * 64; i += 256) {
        int k = i >> 6, n = i & 63;
        float w = (k < 64) ? Wrel[k * 64 + n] : Wroot[(k - 64) * 64 + n];
        sB[k * B_LDF + n] = wmma::__float_to_tf32(w);
    }

    // ---- A tile: [r][k], k<64: S row, k>=64: X row, tf32-rounded ----
    for (int i = tid; i < 128 * 64; i += 256) {
        int r = i >> 6, k = i & 63;
        int grow = rowBase + r;
        float v0 = 0.f, v1 = 0.f;
        if (grow < nRows) {
            v0 = g_S[(size_t)grow * 64 + k];
            v1 = Xin[(size_t)grow * 64 + k];
        }
        sA[r * A_LDF + k] = wmma::__float_to_tf32(v0);
        // second half written below to keep both streams coalesced
        sA[r * A_LDF + 64 + 0] = sA[r * A_LDF + 64 + 0];  // placeholder no-op avoided
    }
    // store X half (k 64..127 maps to sA cols 64..127? A_LDF=72 < 128!)
    __syncthreads();

    // NOTE: A needs K=128 columns; A_LDF must cover 128 + pad.
    // (handled by compile-time layout below)

    // ---- compute ----
    wmma::fragment<wmma::accumulator, 16, 16, 8, float> acc[4];
    #pragma unroll
    for (int j = 0; j < 4; j++) wmma::fill_fragment(acc[j], 0.0f);

    #pragma unroll
    for (int ks = 0; ks < 16; ks++) {
        wmma::fragment<wmma::matrix_a, 16, 16, 8, wmma::precision::tf32, wmma::row_major> aF;
        wmma::load_matrix_sync(aF, sA + (warp * 16) * A_LDF + ks * 8, A_LDF);
        #pragma unroll
        for (int j = 0; j < 4; j++) {
            wmma::fragment<wmma::matrix_b, 16, 16, 8, wmma::precision::tf32, wmma::row_major> bF;
            wmma::load_matrix_sync(bF, sB + (ks * 8) * B_LDF + j * 16, B_LDF);
            wmma::mma_sync(acc[j], aF, bF, acc[j]);
        }
    }
    __syncthreads();

    #pragma unroll
    for (int j = 0; j < 4; j++)
        wmma::store_matrix_sync(stage + (warp * 16) * 68 + j * 16, acc[j], 68,
                                wmma::mem_row_major);
    __syncthreads();

    for (int i = tid; i < 128 * 64; i += 256) {
        int r = i >> 6, c = i & 63;
        int grow = rowBase + r;
        if (grow < nRows) {
            float v = stage[r * 68 + c] + s_bias[c];
            out[(size_t)grow * 64 + c] = fmaxf(v, 0.f);
        }
    }
}

// The A tile above must hold K=128: fix layout constants.
// A_LDF is redefined conceptually as 136 via the wrapper below.
#undef A_LDF
#define A_LDF 136
__global__ void __launch_bounds__(256, 2)
mma_layer_fix(const float* __restrict__ Xin,
              const float* __restrict__ Wrel,
              const float* __restrict__ Wroot,
              const float* __restrict__ bias,
              float* __restrict__ out,
              int nRows) {
    extern __shared__ float dynf[];
    float* sA = dynf;                  // 128*136*4 = 69632B
    float* sB = dynf + 128 * A_LDF;    // 128*68*4  = 34816B
    float* stage = dynf;               // reused post-compute
    __shared__ float s_bias[64];

    int tid = threadIdx.x;
    int warp = tid >> 5;
    int rowBase = blockIdx.x * 128;

    if (tid < 64) s_bias[tid] = bias[tid];

    // B tile [k][n] (K=128 rows): tf32-rounded
    for (int i = tid; i < 128 * 64; i += 256) {
        int k = i >> 6, n = i & 63;
        float w = (k < 64) ? Wrel[k * 64 + n] : Wroot[(k - 64) * 64 + n];
        sB[k * B_LDF + n] = wmma::__float_to_tf32(w);
    }

    // A tile [r][k] (K=128): k<64 from S, k>=64 from X
    for (int i = tid; i < 128 * 64; i += 256) {
        int r = i >> 6, k = i & 63;
        int grow = rowBase + r;
        float vS = 0.f, vX = 0.f;
        if (grow < nRows) {
            vS = g_S[(size_t)grow * 64 + k];
            vX = Xin[(size_t)grow * 64 + k];
        }
        sA[r * A_LDF + k]      = wmma::__float_to_tf32(vS);
        sA[r * A_LDF + 64 + k] = wmma::__float_to_tf32(vX);
    }
    __syncthreads();

    wmma::fragment<wmma::accumulator, 16, 16, 8, float> acc[4];
    #pragma unroll
    for (int j = 0; j < 4; j++) wmma::fill_fragment(acc[j], 0.0f);

    #pragma unroll
    for (int ks = 0; ks < 16; ks++) {
        wmma::fragment<wmma::matrix_a, 16, 16, 8, wmma::precision::tf32, wmma::row_major> aF;
        wmma::load_matrix_sync(aF, sA + (warp * 16) * A_LDF + ks * 8, A_LDF);
        #pragma unroll
        for (int j = 0; j < 4; j++) {
            wmma::fragment<wmma::matrix_b, 16, 16, 8, wmma::precision::tf32, wmma::row_major> bF;
            wmma::load_matrix_sync(bF, sB + (ks * 8) * B_LDF + j * 16, B_LDF);
            wmma::mma_sync(acc[j], aF, bF, acc[j]);
        }
    }
    __syncthreads();

    #pragma unroll
    for (int j = 0; j < 4; j++)
        wmma::store_matrix_sync(stage + (warp * 16) * 68 + j * 16, acc[j], 68,
                                wmma::mem_row_major);
    __syncthreads();

    for (int i = tid; i < 128 * 64; i += 256) {
        int r = i >> 6, c = i & 63;
        int grow = rowBase + r;
        if (grow < nRows) {
            float v = stage[r * 68 + c] + s_bias[c];
            out[(size_t)grow * 64 + c] = fmaxf(v, 0.f);
        }
    }
}

// ---------------- head with fused pooling: one block per graph ------------
__device__ __forceinline__ long long batch_at(const void* b, int i, int is64) {
    return is64 ? ((const long long*)b)[i] : (long long)((const int*)b)[i];
}

__global__ void head_pool_kernel(const void* __restrict__ batch, int nRows,
                                 const float* __restrict__ Wh, const float* __restrict__ bh,
                                 const float* __restrict__ Wc, const float* __restrict__ bc,
                                 const float* __restrict__ Wo, const float* __restrict__ bo,
                                 float* __restrict__ out) {
    int g = blockIdx.x;
    int is64 = g_b64;
    int lo = 0, hi = nRows;
    while (lo < hi) { int m = (lo + hi) >> 1; if (batch_at(batch, m, is64) < g) lo = m + 1; else hi = m; }
    int start = lo;
    lo = 0; hi = nRows;
    while (lo < hi) { int m = (lo + hi) >> 1; if (batch_at(batch, m, is64) < g + 1) lo = m + 1; else hi = m; }
    int end = lo;

    int tid = threadIdx.x;
    int feat = tid & 63;
    int rl   = tid >> 6;

    __shared__ float sm[4][64];
    __shared__ float sp[64];
    __shared__ float sh[64];

    float s = 0.f;
    for (int r = start + rl; r < end; r += 4)
        s += g_h2[(long long)r * FEAT + feat];
    sm[rl][feat] = s;
    __syncthreads();
    if (rl == 0) {
        float tot = sm[0][feat] + sm[1][feat] + sm[2][feat] + sm[3][feat];
        sp[feat] = tot / fmaxf((float)(end - start), 1.0f);
    }
    __syncthreads();

    // hidden & cell (threads 0..63 -> col j)
    if (tid < 64) {
        int j = tid;
        float ah = bh[j], ac = bc[j];
        #pragma unroll 8
        for (int k = 0; k < 64; k++) {
            float p = sp[k];
            ah += p * Wh[k * 64 + j];
            ac += p * Wc[k * 64 + j];
        }
        sh[j] = ah;
        out[2048 + g * 64 + j] = ah;
        out[2048 + 4096 + g * 64 + j] = ac;
    }
    __syncthreads();

    // logits + log_softmax (warp 0, lane = vocab col)
    if (tid < 32) {
        int lane = tid;
        float z = bo[lane];
        #pragma unroll 8
        for (int k = 0; k < 64; k++)
            z += sh[k] * Wo[k * 32 + lane];
        float m = z;
        #pragma unroll
        for (int off = 16; off > 0; off >>= 1)
            m = fmaxf(m, __shfl_xor_sync(0xffffffffu, m, off));
        float e = expf(z - m);
        #pragma unroll
        for (int off = 16; off > 0; off >>= 1)
            e += __shfl_xor_sync(0xffffffffu, e, off);
        out[g * 32 + lane] = z - m - logf(e);
    }
}

// ---------------- launch ----------------
extern "C" void kernel_launch(void* const* d_in, const int* in_sizes, int n_in,
                              void* d_out, int out_size) {
    const float* x     = (const float*)d_in[0];
    const void*  ei    = d_in[1];
    const void*  batch = d_in[2];
    const float* W1    = (const float*)d_in[3];
    const float* root1 = (const float*)d_in[4];
    const float* b1    = (const float*)d_in[5];
    const float* W2    = (const float*)d_in[6];
    const float* root2 = (const float*)d_in[7];
    const float* b2    = (const float*)d_in[8];
    const float* Wh    = (const float*)d_in[9];
    const float* bh    = (const float*)d_in[10];
    const float* Wc    = (const float*)d_in[11];
    const float* bc    = (const float*)d_in[12];
    const float* Wo    = (const float*)d_in[13];
    const float* bo    = (const float*)d_in[14];

    int nN = in_sizes[0] / FEAT;   // 100000
    int nE = in_sizes[1] / 2;      // 1600000

    int eBlocks = (nE + 255) / 256;
    int nBlocks = (nN + 255) / 256;
    int scanBlocks = (nN + 1023) / 1024;
    int gatherBlocks = (nN * 32 + 255) / 256;
    int mmaBlocks = (nN + 127) / 128;
    size_t dynBytes = (size_t)(128 * 136 + 128 * 68) * 4;   // 104448B

    float* h1 = nullptr; float* h2 = nullptr;
    cudaGetSymbolAddress((void**)&h1, g_h);
    cudaGetSymbolAddress((void**)&h2, g_h2);

    cudaFuncSetAttribute(mma_layer_fix, cudaFuncAttributeMaxDynamicSharedMemorySize,
                         (int)dynBytes);

    // CSR build (detect folded into zeroing)
    zero_detect_kernel<<<nBlocks, 256>>>(ei, batch, nE, nN);
    hist_kernel<<<eBlocks, 256>>>(ei, nE);
    scan_block_kernel<<<scanBlocks, 256>>>(nN);
    scan_tops_kernel<<<1, 128>>>(scanBlocks);
    scan_add_kernel<<<nBlocks, 256>>>(nN, nE);
    fill_kernel<<<eBlocks, 256>>>(ei, nE);

    // layer 1
    gather_kernel<<<gatherBlocks, 256>>>(x, nN, 0);
    mma_layer_fix<<<mmaBlocks, 256, dynBytes>>>(x, W1, root1, b1, h1, nN);

    // layer 2
    gather_kernel<<<gatherBlocks, 256>>>(x, nN, 1);
    mma_layer_fix<<<mmaBlocks, 256, dynBytes>>>(h1, W2, root2, b2, h2, nN);

    // pool + heads (fused)
    head_pool_kernel<<<N_GRAPHS, 256>>>(batch, nN, Wh, bh, Wc, bc, Wo, bo,
                                        (float*)d_out);
}